// round 14
// baseline (speedup 1.0000x reference)
#include <cuda_runtime.h>
#include <cuda_fp16.h>
#include <cstdint>

#define B_DIM 16384
#define K_DIM 512
#define T_DIM 16
#define IN_STRIDE 513
#define STAGE_BYTES 16384
#define DSMEM_BYTES (3 * STAGE_BYTES + 128)

#define HALF_ROWS 8192
#define PREP_BLOCKS (HALF_ROWS / 4)              // 2048: 4 rows/block

// ---------------- device scratch ----------------
__device__ __half g_xh[B_DIM * K_DIM];
__device__ __half g_l1h[B_DIM * K_DIM];
__device__ __half g_l2h[B_DIM * K_DIM];
__device__ __half g_w1h[K_DIM * K_DIM];
__device__ __half g_w2h[K_DIM * K_DIM];
__device__ __half g_whh[T_DIM * K_DIM * K_DIM];
__device__ int g_bins[2][T_DIM][HALF_ROWS];      // per-half bins
__device__ int g_cnt[2][T_DIM];

// ---------------- PTX helpers (sm_80-compatible) ----------------
__device__ __forceinline__ uint32_t smem_u32(const void* p) {
    uint32_t a;
    asm("{ .reg .u64 t; cvta.to.shared.u64 t, %1; cvt.u32.u64 %0, t; }" : "=r"(a) : "l"(p));
    return a;
}
__device__ __forceinline__ void cp16(uint32_t dst, const void* src) {
    asm volatile("cp.async.cg.shared.global [%0], [%1], 16;" :: "r"(dst), "l"(src));
}
__device__ __forceinline__ void cp_commit() { asm volatile("cp.async.commit_group;"); }
template <int N>
__device__ __forceinline__ void cp_wait() { asm volatile("cp.async.wait_group %0;" :: "n"(N)); }

__device__ __forceinline__ void ldsm4(uint32_t addr, uint32_t& r0, uint32_t& r1,
                                      uint32_t& r2, uint32_t& r3) {
    asm volatile("ldmatrix.sync.aligned.m8n8.x4.shared.b16 {%0,%1,%2,%3}, [%4];"
                 : "=r"(r0), "=r"(r1), "=r"(r2), "=r"(r3) : "r"(addr));
}
__device__ __forceinline__ void mma16816(float* c, uint32_t a0, uint32_t a1, uint32_t a2,
                                         uint32_t a3, uint32_t b0, uint32_t b1) {
    asm volatile(
        "mma.sync.aligned.m16n8k16.row.col.f32.f16.f16.f32 "
        "{%0,%1,%2,%3}, {%4,%5,%6,%7}, {%8,%9}, {%0,%1,%2,%3};"
        : "+f"(c[0]), "+f"(c[1]), "+f"(c[2]), "+f"(c[3])
        : "r"(a0), "r"(a1), "r"(a2), "r"(a3), "r"(b0), "r"(b1));
}

__device__ __forceinline__ uint32_t pack_h2(__half a, __half b) {
    return (uint32_t)__half_as_ushort(a) | ((uint32_t)__half_as_ushort(b) << 16);
}

// XOR swizzle on 16B chunks: row stride 64B
__device__ __forceinline__ uint32_t swz(uint32_t base, uint32_t row, uint32_t ch) {
    return base + row * 64u + ((ch ^ ((row >> 1) & 3u)) << 4);
}

// ---------------- prep: row-wise pack (R7-proven pattern), per half ----------------
// 4 rows/block, 64 threads/row, 8 cols/thread -> one 16B store; per-half bins.
__global__ void __launch_bounds__(256) k_prep(const float* __restrict__ in,
                                              const float* __restrict__ bh2,
                                              float* __restrict__ out, int half) {
    int r = half * HALF_ROWS + blockIdx.x * 4 + (threadIdx.x >> 6);
    int c0 = (threadIdx.x & 63) * 8;
    const float* src = in + (size_t)r * IN_STRIDE + c0;
    float v[8];
#pragma unroll
    for (int i = 0; i < 8; i++) v[i] = src[i];
    uint32_t hp[4];
#pragma unroll
    for (int i = 0; i < 4; i++)
        hp[i] = pack_h2(__float2half(v[2 * i]), __float2half(v[2 * i + 1]));
    size_t o = (size_t)r * K_DIM + c0;
    *(uint4*)(g_xh + o) = make_uint4(hp[0], hp[1], hp[2], hp[3]);
    if ((threadIdx.x & 63) == 0) {
        int t = (int)in[(size_t)r * IN_STRIDE + K_DIM];
        int pos = atomicAdd(&g_cnt[half][t], 1);
        g_bins[half][t][pos] = r;
        out[r] = bh2[t];
    }
}

// transpose weights [K,N] fp32 -> [N,K] fp16; zeff: 0 -> W1, 1 -> W2, >=2 -> Wh1[zeff-2]
__global__ void k_convw(const float* __restrict__ W1, const float* __restrict__ W2,
                        const float* __restrict__ Wh1, int zbase) {
    __shared__ float tile[32][33];
    int z = blockIdx.z + zbase;
    const float* Wm;
    __half* hi;
    size_t obase;
    if (z == 0)      { Wm = W1; hi = g_w1h; obase = 0; }
    else if (z == 1) { Wm = W2; hi = g_w2h; obase = 0; }
    else {
        int mat = z - 2;
        Wm = Wh1 + (size_t)mat * K_DIM * K_DIM;
        hi = g_whh;
        obase = (size_t)mat * K_DIM * K_DIM;
    }
    int k0 = blockIdx.x * 32, n0 = blockIdx.y * 32;
    for (int ky = threadIdx.y; ky < 32; ky += 8)
        tile[ky][threadIdx.x] = Wm[(size_t)(k0 + ky) * K_DIM + n0 + threadIdx.x];
    __syncthreads();
    for (int ny = threadIdx.y; ny < 32; ny += 8) {
        float v = tile[threadIdx.x][ny];
        hi[obase + (size_t)(n0 + ny) * K_DIM + k0 + threadIdx.x] = __float2half(v);
    }
}

// ---------------- tile loads: 2 sub-tiles (A, W), each 128x32 fp16 ----------------
__device__ __forceinline__ void issue_chunk(
    uint32_t sbuf, int stage, int k0, const int* __restrict__ rows_s, int bn0,
    const __half* __restrict__ A, const __half* __restrict__ Bw, int tid) {
    uint32_t sb = sbuf + (uint32_t)stage * (uint32_t)STAGE_BYTES;
#pragma unroll
    for (int i = 0; i < 4; i++) {
        int idx = tid + i * 256;
        int tile = idx >> 9, w = idx & 511, row = w >> 2, ch = w & 3;
        const __half* src = tile ? Bw : A;
        int gr = tile ? (bn0 + row) : rows_s[row];
        cp16(swz(sb + (uint32_t)tile * 8192u, (uint32_t)row, (uint32_t)ch),
             src + (size_t)gr * K_DIM + k0 + ch * 8);
    }
    cp_commit();
}

// ---------------- per-chunk MMA: single fp16 pass ----------------
__device__ __forceinline__ void compute_chunk(float acc[4][4][4], uint32_t sbuf, int stage,
                                              int lane, int wm, int wn) {
    uint32_t sb = sbuf + (uint32_t)stage * (uint32_t)STAGE_BYTES;
    uint32_t A_t = sb, B_t = sb + 8192u;
    uint32_t lrow = (uint32_t)(lane & 15);
    uint32_t lsel = (uint32_t)(lane >> 4);
#pragma unroll
    for (int kk = 0; kk < 2; kk++) {
        uint32_t ch = (uint32_t)(kk * 2) + lsel;
        uint32_t ah[4][4], bb[2][4];
#pragma unroll
        for (int im = 0; im < 4; im++)
            ldsm4(swz(A_t, (uint32_t)(wm * 64 + im * 16) + lrow, ch),
                  ah[im][0], ah[im][1], ah[im][2], ah[im][3]);
#pragma unroll
        for (int jn = 0; jn < 2; jn++)
            ldsm4(swz(B_t, (uint32_t)(wn * 32 + jn * 16) + lrow, ch),
                  bb[jn][0], bb[jn][1], bb[jn][2], bb[jn][3]);
#pragma unroll
        for (int im = 0; im < 4; im++)
#pragma unroll
            for (int j = 0; j < 4; j++)
                mma16816(acc[im][j], ah[im][0], ah[im][1], ah[im][2], ah[im][3],
                         bb[j >> 1][j & 1], bb[j >> 1][(j & 1) + 2]);
    }
}

// 3-stage pipeline, one barrier per iteration.
__device__ __forceinline__ void mma_mainloop(
    float acc[4][4][4], uint32_t sbuf, const int* __restrict__ rows_s, int bn0,
    const __half* __restrict__ A, const __half* __restrict__ Bw,
    int tid, int lane, int wm, int wn) {
    issue_chunk(sbuf, 0, 0, rows_s, bn0, A, Bw, tid);
    issue_chunk(sbuf, 1, 32, rows_s, bn0, A, Bw, tid);
    int stage = 0;
#pragma unroll 1
    for (int c = 0; c < 16; c++) {
        if (c >= 14) cp_wait<0>(); else cp_wait<1>();
        __syncthreads();
        if (c + 2 < 16) {
            int ns = stage + 2; if (ns >= 3) ns -= 3;
            issue_chunk(sbuf, ns, (c + 2) * 32, rows_s, bn0, A, Bw, tid);
        }
        compute_chunk(acc, sbuf, stage, lane, wm, wn);
        if (++stage == 3) stage = 0;
    }
}

// ---------------- GEMM + bias + relu -> fp16 (moff: m-tile offset) ----------------
__global__ void __launch_bounds__(256) k_mm(
    const __half* __restrict__ A, const __half* __restrict__ Bw,
    const float* __restrict__ bias, __half* __restrict__ C, int moff) {
    extern __shared__ char dsmem[];
    __shared__ int rows_s[128];
    __shared__ float sbias[128];
    uint32_t sbuf = (smem_u32(dsmem) + 127u) & ~127u;

    int tid = threadIdx.x, lane = tid & 31, wid = tid >> 5;
    int wm = wid & 1, wn = wid >> 1;
    int m0 = (blockIdx.x + moff) * 128, n0 = blockIdx.y * 128;

    if (tid < 128) { rows_s[tid] = m0 + tid; sbias[tid] = bias[n0 + tid]; }
    __syncthreads();

    float acc[4][4][4];
#pragma unroll
    for (int a = 0; a < 4; a++)
#pragma unroll
        for (int b = 0; b < 4; b++)
#pragma unroll
            for (int d = 0; d < 4; d++) acc[a][b][d] = 0.f;

    mma_mainloop(acc, sbuf, rows_s, n0, A, Bw, tid, lane, wm, wn);

#pragma unroll
    for (int im = 0; im < 4; im++) {
        int r0 = m0 + wm * 64 + im * 16 + (lane >> 2);
#pragma unroll
        for (int j = 0; j < 4; j++) {
            int nloc = wn * 32 + j * 8 + (lane & 3) * 2;
            float v0 = fmaxf(acc[im][j][0] + sbias[nloc],     0.f);
            float v1 = fmaxf(acc[im][j][1] + sbias[nloc + 1], 0.f);
            float v2 = fmaxf(acc[im][j][2] + sbias[nloc],     0.f);
            float v3 = fmaxf(acc[im][j][3] + sbias[nloc + 1], 0.f);
            size_t o0 = (size_t)r0 * K_DIM + n0 + nloc;
            size_t o1 = (size_t)(r0 + 8) * K_DIM + n0 + nloc;
            *(uint32_t*)(C + o0) = pack_h2(__float2half(v0), __float2half(v1));
            *(uint32_t*)(C + o1) = pack_h2(__float2half(v2), __float2half(v3));
        }
    }
}

// ---------------- head: gathered GEMM + relu + dot(Wh2) reduce (per half) ----------------
__global__ void __launch_bounds__(256) k_head(
    const __half* __restrict__ l2h, const __half* __restrict__ whh,
    const float* __restrict__ bh1, const float* __restrict__ Wh2,
    float* __restrict__ out, int half) {
    int t = blockIdx.z;
    int cnt = g_cnt[half][t];
    int tile = blockIdx.x;
    if (tile * 128 >= cnt) return;
    int n0 = blockIdx.y * 128;

    extern __shared__ char dsmem[];
    __shared__ int rows_s[128];
    __shared__ float sbh1[128];
    __shared__ float swh2[128];
    uint32_t sbuf = (smem_u32(dsmem) + 127u) & ~127u;

    int tid = threadIdx.x, lane = tid & 31, wid = tid >> 5;
    int wm = wid & 1, wn = wid >> 1;

    if (tid < 128) {
        int idx = tile * 128 + tid;
        rows_s[tid] = g_bins[half][t][idx < cnt ? idx : cnt - 1];
        sbh1[tid] = bh1[t * K_DIM + n0 + tid];
        swh2[tid] = Wh2[t * K_DIM + n0 + tid];
    }
    __syncthreads();

    float acc[4][4][4];
#pragma unroll
    for (int a = 0; a < 4; a++)
#pragma unroll
        for (int b = 0; b < 4; b++)
#pragma unroll
            for (int d = 0; d < 4; d++) acc[a][b][d] = 0.f;

    mma_mainloop(acc, sbuf, rows_s, n0, l2h,
                 whh + (size_t)t * K_DIM * K_DIM, tid, lane, wm, wn);

#pragma unroll
    for (int im = 0; im < 4; im++) {
        float p0 = 0.f, p1 = 0.f;
#pragma unroll
        for (int j = 0; j < 4; j++) {
            int nloc = wn * 32 + j * 8 + (lane & 3) * 2;
            float w0 = swh2[nloc], w1 = swh2[nloc + 1];
            float q0 = sbh1[nloc], q1 = sbh1[nloc + 1];
            p0 = fmaf(fmaxf(acc[im][j][0] + q0, 0.f), w0, p0);
            p0 = fmaf(fmaxf(acc[im][j][1] + q1, 0.f), w1, p0);
            p1 = fmaf(fmaxf(acc[im][j][2] + q0, 0.f), w0, p1);
            p1 = fmaf(fmaxf(acc[im][j][3] + q1, 0.f), w1, p1);
        }
        p0 += __shfl_xor_sync(0xffffffffu, p0, 1);
        p0 += __shfl_xor_sync(0xffffffffu, p0, 2);
        p1 += __shfl_xor_sync(0xffffffffu, p1, 1);
        p1 += __shfl_xor_sync(0xffffffffu, p1, 2);
        if ((lane & 3) == 0) {
            int rl0 = wm * 64 + im * 16 + (lane >> 2);
            int rl1 = rl0 + 8;
            if (tile * 128 + rl0 < cnt) atomicAdd(&out[rows_s[rl0]], p0);
            if (tile * 128 + rl1 < cnt) atomicAdd(&out[rows_s[rl1]], p1);
        }
    }
}

// ---------------- launch: two independent half-batch chains (R12 structure) ----------------
extern "C" void kernel_launch(void* const* d_in, const int* in_sizes, int n_in,
                              void* d_out, int out_size) {
    const float* in  = (const float*)d_in[0];
    const float* W1  = (const float*)d_in[1];
    const float* b1  = (const float*)d_in[2];
    const float* W2  = (const float*)d_in[3];
    const float* b2  = (const float*)d_in[4];
    const float* Wh1 = (const float*)d_in[5];
    const float* bh1 = (const float*)d_in[6];
    const float* Wh2 = (const float*)d_in[7];
    const float* bh2 = (const float*)d_in[8];
    float* out = (float*)d_out;

    static cudaStream_t s1 = nullptr, s2 = nullptr;
    static cudaEvent_t evRoot = nullptr, evW12 = nullptr, evWh = nullptr, evDoneB = nullptr;
    if (!s1) {
        cudaStreamCreateWithFlags(&s1, cudaStreamNonBlocking);
        cudaStreamCreateWithFlags(&s2, cudaStreamNonBlocking);
        cudaEventCreateWithFlags(&evRoot, cudaEventDisableTiming);
        cudaEventCreateWithFlags(&evW12, cudaEventDisableTiming);
        cudaEventCreateWithFlags(&evWh, cudaEventDisableTiming);
        cudaEventCreateWithFlags(&evDoneB, cudaEventDisableTiming);
        cudaFuncSetAttribute(k_mm,   cudaFuncAttributeMaxDynamicSharedMemorySize, DSMEM_BYTES);
        cudaFuncSetAttribute(k_head, cudaFuncAttributeMaxDynamicSharedMemorySize, DSMEM_BYTES);
    }

    __half *xh, *l1h, *l2h, *w1h, *w2h, *whh;
    int* pcnt;
    cudaGetSymbolAddress((void**)&xh,  g_xh);
    cudaGetSymbolAddress((void**)&l1h, g_l1h);
    cudaGetSymbolAddress((void**)&l2h, g_l2h);
    cudaGetSymbolAddress((void**)&w1h, g_w1h);
    cudaGetSymbolAddress((void**)&w2h, g_w2h);
    cudaGetSymbolAddress((void**)&whh, g_whh);
    cudaGetSymbolAddress((void**)&pcnt, g_cnt);

    // root: zero counters via memset node (no kernel launch)
    cudaMemsetAsync(pcnt, 0, 2 * T_DIM * sizeof(int), 0);
    cudaEventRecord(evRoot, 0);

    // s1: weight conversions
    cudaStreamWaitEvent(s1, evRoot, 0);
    k_convw<<<dim3(16, 16, 2),  dim3(32, 8), 0, s1>>>(W1, W2, Wh1, 0);  // W1, W2
    cudaEventRecord(evW12, s1);
    k_convw<<<dim3(16, 16, 16), dim3(32, 8), 0, s1>>>(W1, W2, Wh1, 2);  // Wh1 only
    cudaEventRecord(evWh, s1);

    // chain B on s2: prepB -> mm1B -> mm2B -> headB
    cudaStreamWaitEvent(s2, evRoot, 0);
    k_prep<<<PREP_BLOCKS, 256, 0, s2>>>(in, bh2, out, 1);
    cudaStreamWaitEvent(s2, evW12, 0);
    k_mm<<<dim3(64, 4), 256, DSMEM_BYTES, s2>>>(xh, w1h, b1, l1h, 64);
    k_mm<<<dim3(64, 4), 256, DSMEM_BYTES, s2>>>(l1h, w2h, b2, l2h, 64);
    cudaStreamWaitEvent(s2, evWh, 0);
    k_head<<<dim3(64, 4, 16), 256, DSMEM_BYTES, s2>>>(l2h, whh, bh1, Wh2, out, 1);
    cudaEventRecord(evDoneB, s2);

    // chain A on stream 0: prepA -> mm1A -> mm2A -> headA
    k_prep<<<PREP_BLOCKS, 256>>>(in, bh2, out, 0);
    cudaStreamWaitEvent(0, evW12, 0);
    k_mm<<<dim3(64, 4), 256, DSMEM_BYTES>>>(xh, w1h, b1, l1h, 0);
    k_mm<<<dim3(64, 4), 256, DSMEM_BYTES>>>(l1h, w2h, b2, l2h, 0);
    cudaStreamWaitEvent(0, evWh, 0);
    k_head<<<dim3(64, 4, 16), 256, DSMEM_BYTES>>>(l2h, whh, bh1, Wh2, out, 0);

    // join chain B back into the captured stream
    cudaStreamWaitEvent(0, evDoneB, 0);
}

// round 15
// speedup vs baseline: 1.0437x; 1.0437x over previous
#include <cuda_runtime.h>
#include <cuda_fp16.h>
#include <cstdint>

#define B_DIM 16384
#define K_DIM 512
#define T_DIM 16
#define IN_STRIDE 513
#define STAGE_BYTES 32768
#define DSMEM_BYTES (3 * STAGE_BYTES + 128)

#define HALF_ROWS 8192
#define PREP_BLOCKS (HALF_ROWS / 4)              // 2048: 4 rows/block

// ---------------- device scratch ----------------
__device__ __half g_xh[B_DIM * K_DIM];
__device__ __half g_l1h[B_DIM * K_DIM];
__device__ __half g_l2h[B_DIM * K_DIM];
__device__ __half g_w1h[K_DIM * K_DIM];
__device__ __half g_w2h[K_DIM * K_DIM];
__device__ __half g_whh[T_DIM * K_DIM * K_DIM];
__device__ int g_bins[2][T_DIM][HALF_ROWS];      // per-half bins
__device__ int g_cnt[2][T_DIM];

// ---------------- PTX helpers (sm_80-compatible) ----------------
__device__ __forceinline__ uint32_t smem_u32(const void* p) {
    uint32_t a;
    asm("{ .reg .u64 t; cvta.to.shared.u64 t, %1; cvt.u32.u64 %0, t; }" : "=r"(a) : "l"(p));
    return a;
}
__device__ __forceinline__ void cp16(uint32_t dst, const void* src) {
    asm volatile("cp.async.cg.shared.global [%0], [%1], 16;" :: "r"(dst), "l"(src));
}
__device__ __forceinline__ void cp_commit() { asm volatile("cp.async.commit_group;"); }
template <int N>
__device__ __forceinline__ void cp_wait() { asm volatile("cp.async.wait_group %0;" :: "n"(N)); }

__device__ __forceinline__ void ldsm4(uint32_t addr, uint32_t& r0, uint32_t& r1,
                                      uint32_t& r2, uint32_t& r3) {
    asm volatile("ldmatrix.sync.aligned.m8n8.x4.shared.b16 {%0,%1,%2,%3}, [%4];"
                 : "=r"(r0), "=r"(r1), "=r"(r2), "=r"(r3) : "r"(addr));
}
__device__ __forceinline__ void mma16816(float* c, uint32_t a0, uint32_t a1, uint32_t a2,
                                         uint32_t a3, uint32_t b0, uint32_t b1) {
    asm volatile(
        "mma.sync.aligned.m16n8k16.row.col.f32.f16.f16.f32 "
        "{%0,%1,%2,%3}, {%4,%5,%6,%7}, {%8,%9}, {%0,%1,%2,%3};"
        : "+f"(c[0]), "+f"(c[1]), "+f"(c[2]), "+f"(c[3])
        : "r"(a0), "r"(a1), "r"(a2), "r"(a3), "r"(b0), "r"(b1));
}

__device__ __forceinline__ uint32_t pack_h2(__half a, __half b) {
    return (uint32_t)__half_as_ushort(a) | ((uint32_t)__half_as_ushort(b) << 16);
}

// XOR swizzle on 16B chunks: row stride 64B
__device__ __forceinline__ uint32_t swz(uint32_t base, uint32_t row, uint32_t ch) {
    return base + row * 64u + ((ch ^ ((row >> 1) & 3u)) << 4);
}

// ---------------- prep: row-wise pack, per half ----------------
__global__ void __launch_bounds__(256) k_prep(const float* __restrict__ in,
                                              const float* __restrict__ bh2,
                                              float* __restrict__ out, int half) {
    int r = half * HALF_ROWS + blockIdx.x * 4 + (threadIdx.x >> 6);
    int c0 = (threadIdx.x & 63) * 8;
    const float* src = in + (size_t)r * IN_STRIDE + c0;
    float v[8];
#pragma unroll
    for (int i = 0; i < 8; i++) v[i] = src[i];
    uint32_t hp[4];
#pragma unroll
    for (int i = 0; i < 4; i++)
        hp[i] = pack_h2(__float2half(v[2 * i]), __float2half(v[2 * i + 1]));
    size_t o = (size_t)r * K_DIM + c0;
    *(uint4*)(g_xh + o) = make_uint4(hp[0], hp[1], hp[2], hp[3]);
    if ((threadIdx.x & 63) == 0) {
        int t = (int)in[(size_t)r * IN_STRIDE + K_DIM];
        int pos = atomicAdd(&g_cnt[half][t], 1);
        g_bins[half][t][pos] = r;
        out[r] = bh2[t];
    }
}

// transpose weights [K,N] fp32 -> [N,K] fp16; zeff: 0 -> W1, 1 -> W2, >=2 -> Wh1[zeff-2]
__global__ void k_convw(const float* __restrict__ W1, const float* __restrict__ W2,
                        const float* __restrict__ Wh1, int zbase) {
    __shared__ float tile[32][33];
    int z = blockIdx.z + zbase;
    const float* Wm;
    __half* hi;
    size_t obase;
    if (z == 0)      { Wm = W1; hi = g_w1h; obase = 0; }
    else if (z == 1) { Wm = W2; hi = g_w2h; obase = 0; }
    else {
        int mat = z - 2;
        Wm = Wh1 + (size_t)mat * K_DIM * K_DIM;
        hi = g_whh;
        obase = (size_t)mat * K_DIM * K_DIM;
    }
    int k0 = blockIdx.x * 32, n0 = blockIdx.y * 32;
    for (int ky = threadIdx.y; ky < 32; ky += 8)
        tile[ky][threadIdx.x] = Wm[(size_t)(k0 + ky) * K_DIM + n0 + threadIdx.x];
    __syncthreads();
    for (int ny = threadIdx.y; ny < 32; ny += 8) {
        float v = tile[threadIdx.x][ny];
        hi[obase + (size_t)(n0 + ny) * K_DIM + k0 + threadIdx.x] = __float2half(v);
    }
}

// ---------------- stage loads: K=64 per stage, two 16KB sub-chunks ----------------
// sub-chunk layout (per 16KB): A[128x32] at +0, W[128x32] at +8192.
__device__ __forceinline__ void issue_stage(
    uint32_t sbuf, int stage, int k0, const int* __restrict__ rows_s, int bn0,
    const __half* __restrict__ A, const __half* __restrict__ Bw, int tid) {
    uint32_t sb = sbuf + (uint32_t)stage * (uint32_t)STAGE_BYTES;
#pragma unroll
    for (int i = 0; i < 8; i++) {
        int idx = tid + i * 256;
        int sub = idx >> 10;                 // 0,1: which K=32 sub-chunk
        int w = idx & 1023;
        int tile = w >> 9;                   // 0: A, 1: W
        int ww = w & 511;
        int row = ww >> 2, ch = ww & 3;
        const __half* src = tile ? Bw : A;
        int gr = tile ? (bn0 + row) : rows_s[row];
        cp16(swz(sb + (uint32_t)sub * 16384u + (uint32_t)tile * 8192u,
                 (uint32_t)row, (uint32_t)ch),
             src + (size_t)gr * K_DIM + k0 + sub * 32 + ch * 8);
    }
    cp_commit();
}

// ---------------- per-stage MMA: K=64 (two sub-chunks), single fp16 pass ----------------
__device__ __forceinline__ void compute_stage(float acc[4][4][4], uint32_t sbuf, int stage,
                                              int lane, int wm, int wn) {
    uint32_t sb = sbuf + (uint32_t)stage * (uint32_t)STAGE_BYTES;
    uint32_t lrow = (uint32_t)(lane & 15);
    uint32_t lsel = (uint32_t)(lane >> 4);
#pragma unroll
    for (int sub = 0; sub < 2; sub++) {
        uint32_t A_t = sb + (uint32_t)sub * 16384u;
        uint32_t B_t = A_t + 8192u;
#pragma unroll
        for (int kk = 0; kk < 2; kk++) {
            uint32_t ch = (uint32_t)(kk * 2) + lsel;
            uint32_t ah[4][4], bb[2][4];
#pragma unroll
            for (int im = 0; im < 4; im++)
                ldsm4(swz(A_t, (uint32_t)(wm * 64 + im * 16) + lrow, ch),
                      ah[im][0], ah[im][1], ah[im][2], ah[im][3]);
#pragma unroll
            for (int jn = 0; jn < 2; jn++)
                ldsm4(swz(B_t, (uint32_t)(wn * 32 + jn * 16) + lrow, ch),
                      bb[jn][0], bb[jn][1], bb[jn][2], bb[jn][3]);
#pragma unroll
            for (int im = 0; im < 4; im++)
#pragma unroll
                for (int j = 0; j < 4; j++)
                    mma16816(acc[im][j], ah[im][0], ah[im][1], ah[im][2], ah[im][3],
                             bb[j >> 1][j & 1], bb[j >> 1][(j & 1) + 2]);
        }
    }
}

// 3-stage pipeline over 8 K=64 stages, one barrier per iteration.
__device__ __forceinline__ void mma_mainloop(
    float acc[4][4][4], uint32_t sbuf, const int* __restrict__ rows_s, int bn0,
    const __half* __restrict__ A, const __half* __restrict__ Bw,
    int tid, int lane, int wm, int wn) {
    issue_stage(sbuf, 0, 0, rows_s, bn0, A, Bw, tid);
    issue_stage(sbuf, 1, 64, rows_s, bn0, A, Bw, tid);
    int stage = 0;
#pragma unroll 1
    for (int c = 0; c < 8; c++) {
        if (c >= 6) cp_wait<0>(); else cp_wait<1>();
        __syncthreads();
        if (c + 2 < 8) {
            int ns = stage + 2; if (ns >= 3) ns -= 3;
            issue_stage(sbuf, ns, (c + 2) * 64, rows_s, bn0, A, Bw, tid);
        }
        compute_stage(acc, sbuf, stage, lane, wm, wn);
        if (++stage == 3) stage = 0;
    }
}

// ---------------- GEMM + bias + relu -> fp16 (moff: m-tile offset) ----------------
__global__ void __launch_bounds__(256) k_mm(
    const __half* __restrict__ A, const __half* __restrict__ Bw,
    const float* __restrict__ bias, __half* __restrict__ C, int moff) {
    extern __shared__ char dsmem[];
    __shared__ int rows_s[128];
    __shared__ float sbias[128];
    uint32_t sbuf = (smem_u32(dsmem) + 127u) & ~127u;

    int tid = threadIdx.x, lane = tid & 31, wid = tid >> 5;
    int wm = wid & 1, wn = wid >> 1;
    int m0 = (blockIdx.x + moff) * 128, n0 = blockIdx.y * 128;

    if (tid < 128) { rows_s[tid] = m0 + tid; sbias[tid] = bias[n0 + tid]; }
    __syncthreads();

    float acc[4][4][4];
#pragma unroll
    for (int a = 0; a < 4; a++)
#pragma unroll
        for (int b = 0; b < 4; b++)
#pragma unroll
            for (int d = 0; d < 4; d++) acc[a][b][d] = 0.f;

    mma_mainloop(acc, sbuf, rows_s, n0, A, Bw, tid, lane, wm, wn);

#pragma unroll
    for (int im = 0; im < 4; im++) {
        int r0 = m0 + wm * 64 + im * 16 + (lane >> 2);
#pragma unroll
        for (int j = 0; j < 4; j++) {
            int nloc = wn * 32 + j * 8 + (lane & 3) * 2;
            float v0 = fmaxf(acc[im][j][0] + sbias[nloc],     0.f);
            float v1 = fmaxf(acc[im][j][1] + sbias[nloc + 1], 0.f);
            float v2 = fmaxf(acc[im][j][2] + sbias[nloc],     0.f);
            float v3 = fmaxf(acc[im][j][3] + sbias[nloc + 1], 0.f);
            size_t o0 = (size_t)r0 * K_DIM + n0 + nloc;
            size_t o1 = (size_t)(r0 + 8) * K_DIM + n0 + nloc;
            *(uint32_t*)(C + o0) = pack_h2(__float2half(v0), __float2half(v1));
            *(uint32_t*)(C + o1) = pack_h2(__float2half(v2), __float2half(v3));
        }
    }
}

// ---------------- head: gathered GEMM + relu + dot(Wh2) reduce (per half) ----------------
__global__ void __launch_bounds__(256) k_head(
    const __half* __restrict__ l2h, const __half* __restrict__ whh,
    const float* __restrict__ bh1, const float* __restrict__ Wh2,
    float* __restrict__ out, int half) {
    int t = blockIdx.z;
    int cnt = g_cnt[half][t];
    int tile = blockIdx.x;
    if (tile * 128 >= cnt) return;
    int n0 = blockIdx.y * 128;

    extern __shared__ char dsmem[];
    __shared__ int rows_s[128];
    __shared__ float sbh1[128];
    __shared__ float swh2[128];
    uint32_t sbuf = (smem_u32(dsmem) + 127u) & ~127u;

    int tid = threadIdx.x, lane = tid & 31, wid = tid >> 5;
    int wm = wid & 1, wn = wid >> 1;

    if (tid < 128) {
        int idx = tile * 128 + tid;
        rows_s[tid] = g_bins[half][t][idx < cnt ? idx : cnt - 1];
        sbh1[tid] = bh1[t * K_DIM + n0 + tid];
        swh2[tid] = Wh2[t * K_DIM + n0 + tid];
    }
    __syncthreads();

    float acc[4][4][4];
#pragma unroll
    for (int a = 0; a < 4; a++)
#pragma unroll
        for (int b = 0; b < 4; b++)
#pragma unroll
            for (int d = 0; d < 4; d++) acc[a][b][d] = 0.f;

    mma_mainloop(acc, sbuf, rows_s, n0, l2h,
                 whh + (size_t)t * K_DIM * K_DIM, tid, lane, wm, wn);

#pragma unroll
    for (int im = 0; im < 4; im++) {
        float p0 = 0.f, p1 = 0.f;
#pragma unroll
        for (int j = 0; j < 4; j++) {
            int nloc = wn * 32 + j * 8 + (lane & 3) * 2;
            float w0 = swh2[nloc], w1 = swh2[nloc + 1];
            float q0 = sbh1[nloc], q1 = sbh1[nloc + 1];
            p0 = fmaf(fmaxf(acc[im][j][0] + q0, 0.f), w0, p0);
            p0 = fmaf(fmaxf(acc[im][j][1] + q1, 0.f), w1, p0);
            p1 = fmaf(fmaxf(acc[im][j][2] + q0, 0.f), w0, p1);
            p1 = fmaf(fmaxf(acc[im][j][3] + q1, 0.f), w1, p1);
        }
        p0 += __shfl_xor_sync(0xffffffffu, p0, 1);
        p0 += __shfl_xor_sync(0xffffffffu, p0, 2);
        p1 += __shfl_xor_sync(0xffffffffu, p1, 1);
        p1 += __shfl_xor_sync(0xffffffffu, p1, 2);
        if ((lane & 3) == 0) {
            int rl0 = wm * 64 + im * 16 + (lane >> 2);
            int rl1 = rl0 + 8;
            if (tile * 128 + rl0 < cnt) atomicAdd(&out[rows_s[rl0]], p0);
            if (tile * 128 + rl1 < cnt) atomicAdd(&out[rows_s[rl1]], p1);
        }
    }
}

// ---------------- launch: two independent half-batch chains ----------------
extern "C" void kernel_launch(void* const* d_in, const int* in_sizes, int n_in,
                              void* d_out, int out_size) {
    const float* in  = (const float*)d_in[0];
    const float* W1  = (const float*)d_in[1];
    const float* b1  = (const float*)d_in[2];
    const float* W2  = (const float*)d_in[3];
    const float* b2  = (const float*)d_in[4];
    const float* Wh1 = (const float*)d_in[5];
    const float* bh1 = (const float*)d_in[6];
    const float* Wh2 = (const float*)d_in[7];
    const float* bh2 = (const float*)d_in[8];
    float* out = (float*)d_out;

    static cudaStream_t s1 = nullptr, s2 = nullptr;
    static cudaEvent_t evRoot = nullptr, evW12 = nullptr, evWh = nullptr, evDoneB = nullptr;
    if (!s1) {
        cudaStreamCreateWithFlags(&s1, cudaStreamNonBlocking);
        cudaStreamCreateWithFlags(&s2, cudaStreamNonBlocking);
        cudaEventCreateWithFlags(&evRoot, cudaEventDisableTiming);
        cudaEventCreateWithFlags(&evW12, cudaEventDisableTiming);
        cudaEventCreateWithFlags(&evWh, cudaEventDisableTiming);
        cudaEventCreateWithFlags(&evDoneB, cudaEventDisableTiming);
        cudaFuncSetAttribute(k_mm,   cudaFuncAttributeMaxDynamicSharedMemorySize, DSMEM_BYTES);
        cudaFuncSetAttribute(k_head, cudaFuncAttributeMaxDynamicSharedMemorySize, DSMEM_BYTES);
    }

    __half *xh, *l1h, *l2h, *w1h, *w2h, *whh;
    int* pcnt;
    cudaGetSymbolAddress((void**)&xh,  g_xh);
    cudaGetSymbolAddress((void**)&l1h, g_l1h);
    cudaGetSymbolAddress((void**)&l2h, g_l2h);
    cudaGetSymbolAddress((void**)&w1h, g_w1h);
    cudaGetSymbolAddress((void**)&w2h, g_w2h);
    cudaGetSymbolAddress((void**)&whh, g_whh);
    cudaGetSymbolAddress((void**)&pcnt, g_cnt);

    // root: zero counters via memset node
    cudaMemsetAsync(pcnt, 0, 2 * T_DIM * sizeof(int), 0);
    cudaEventRecord(evRoot, 0);

    // s1: weight conversions
    cudaStreamWaitEvent(s1, evRoot, 0);
    k_convw<<<dim3(16, 16, 2),  dim3(32, 8), 0, s1>>>(W1, W2, Wh1, 0);  // W1, W2
    cudaEventRecord(evW12, s1);
    k_convw<<<dim3(16, 16, 16), dim3(32, 8), 0, s1>>>(W1, W2, Wh1, 2);  // Wh1 only
    cudaEventRecord(evWh, s1);

    // chain B on s2: prepB -> mm1B -> mm2B -> headB
    cudaStreamWaitEvent(s2, evRoot, 0);
    k_prep<<<PREP_BLOCKS, 256, 0, s2>>>(in, bh2, out, 1);
    cudaStreamWaitEvent(s2, evW12, 0);
    k_mm<<<dim3(64, 4), 256, DSMEM_BYTES, s2>>>(xh, w1h, b1, l1h, 64);
    k_mm<<<dim3(64, 4), 256, DSMEM_BYTES, s2>>>(l1h, w2h, b2, l2h, 64);
    cudaStreamWaitEvent(s2, evWh, 0);
    k_head<<<dim3(64, 4, 16), 256, DSMEM_BYTES, s2>>>(l2h, whh, bh1, Wh2, out, 1);
    cudaEventRecord(evDoneB, s2);

    // chain A on stream 0: prepA -> mm1A -> mm2A -> headA
    k_prep<<<PREP_BLOCKS, 256>>>(in, bh2, out, 0);
    cudaStreamWaitEvent(0, evW12, 0);
    k_mm<<<dim3(64, 4), 256, DSMEM_BYTES>>>(xh, w1h, b1, l1h, 0);
    k_mm<<<dim3(64, 4), 256, DSMEM_BYTES>>>(l1h, w2h, b2, l2h, 0);
    cudaStreamWaitEvent(0, evWh, 0);
    k_head<<<dim3(64, 4, 16), 256, DSMEM_BYTES>>>(l2h, whh, bh1, Wh2, out, 0);

    // join chain B back into the captured stream
    cudaStreamWaitEvent(0, evDoneB, 0);
}